// round 11
// baseline (speedup 1.0000x reference)
#include <cuda_runtime.h>
#include <cuda_bf16.h>
#include <cstdint>

// Problem shapes (fixed by the dataset's setup_inputs)
constexpr int B = 16;
constexpr int S = 512;
constexpr int D = 768;     // span_dim
constexpr int E = 128;     // distance embedding dim
constexpr int T = 64;
constexpr int O = 64;
constexpr int P = T * O;            // 4096 pairs per batch
constexpr int OUT_D = 2 * D + E;    // 1664 floats per output row
constexpr int D4 = D / 4;           // 192 float4
constexpr int E4 = E / 4;           // 32 float4
constexpr int OUT_D4 = OUT_D / 4;   // 416 float4
constexpr int NBINS = 14;

// bucket = (# bins <= width) - 1; bins[0]=0 and width>=0,
// so bucket = sum_{i=1..13} (width >= bins[i]).
__constant__ int c_bins[NBINS] = {0, 1, 2, 3, 4, 5, 7, 8, 15, 16, 31, 32, 63, 64};

__device__ __forceinline__ int bucketize(int w) {
    int bucket = 0;
#pragma unroll
    for (int i = 1; i < NBINS; ++i)
        bucket += (w >= c_bins[i]) ? 1 : 0;
    return bucket;
}

// Exactly the R4 structure (best: 61.9us) with ONE change: default-policy
// stores instead of __stcs streaming stores. Every warp writes fully-covered
// 128B lines; default policy lets L2 accumulate and evict complete lines as
// bursts, potentially improving DRAM write efficiency vs sector-granular
// streaming drain. A/B experiment on the store path.
__global__ __launch_bounds__(192, 10)
void pair_rep_kernel(const float4* __restrict__ spans,      // [B,S,D/4]
                     const float4* __restrict__ dist_emb,   // [14,E/4]
                     const int2*   __restrict__ span_idx,   // [S]
                     const int*    __restrict__ tgt,        // [B,T]
                     const int*    __restrict__ opi,        // [B,O]
                     float4*       __restrict__ out)        // [B*P, OUT_D/4]
{
    const int blk = blockIdx.x;            // 0 .. B*T*(O/2)-1
    const int b   = blk >> 11;             // / 2048
    const int r   = blk & 2047;
    const int t   = r >> 5;                // / 32
    const int g   = r & 31;                // opinion pair group
    const int o0  = 2 * g;

    const int ti  = __ldg(&tgt[b * T + t]);
    const int oiA = __ldg(&opi[b * O + o0]);
    const int oiB = __ldg(&opi[b * O + o0 + 1]);

    const int2 ab = __ldg(&span_idx[ti]);
    const int2 cdA = __ldg(&span_idx[oiA]);
    const int2 cdB = __ldg(&span_idx[oiB]);
    const int wA = min(abs(ab.y - cdA.x), abs(ab.x - cdA.y));
    const int wB = min(abs(ab.y - cdB.x), abs(ab.x - cdB.y));
    const int bkA = bucketize(wA);
    const int bkB = bucketize(wB);

    const int tid = threadIdx.x;           // 0..191 == D4

    const float4* spb = spans + (size_t)b * S * D4;

    // Hoist all independent loads (vt reused for both rows)
    const float4 vt  = __ldg(&spb[(size_t)ti  * D4 + tid]);
    const float4 voA = __ldg(&spb[(size_t)oiA * D4 + tid]);
    const float4 voB = __ldg(&spb[(size_t)oiB * D4 + tid]);
    float4 vdA, vdB;
    if (tid < E4) {
        vdA = __ldg(&dist_emb[(size_t)bkA * E4 + tid]);
        vdB = __ldg(&dist_emb[(size_t)bkB * E4 + tid]);
    }

    float4* dst = out + ((size_t)b * P + (size_t)t * O + o0) * OUT_D4;

    // Row A — default-policy stores (L2 line accumulation + burst evict)
    dst[tid] = vt;
    dst[D4 + tid] = voA;
    if (tid < E4) dst[2 * D4 + tid] = vdA;
    // Row B
    dst[OUT_D4 + tid] = vt;
    dst[OUT_D4 + D4 + tid] = voB;
    if (tid < E4) dst[OUT_D4 + 2 * D4 + tid] = vdB;
}

extern "C" void kernel_launch(void* const* d_in, const int* in_sizes, int n_in,
                              void* d_out, int out_size)
{
    // metadata order: spans, dist_emb, span_indices, target_indices, opinion_indices
    const float4* spans    = (const float4*)d_in[0];
    const float4* dist_emb = (const float4*)d_in[1];
    const int2*   span_idx = (const int2*)  d_in[2];
    const int*    tgt      = (const int*)   d_in[3];
    const int*    opi      = (const int*)   d_in[4];
    float4*       out      = (float4*)d_out;

    dim3 grid(B * T * (O / 2));   // 32768 blocks, two rows each
    dim3 block(192);
    pair_rep_kernel<<<grid, block>>>(spans, dist_emb, span_idx, tgt, opi, out);
}

// round 12
// speedup vs baseline: 1.0874x; 1.0874x over previous
#include <cuda_runtime.h>
#include <cuda_bf16.h>
#include <cstdint>

// Problem shapes (fixed by the dataset's setup_inputs)
constexpr int B = 16;
constexpr int S = 512;
constexpr int D = 768;     // span_dim
constexpr int E = 128;     // distance embedding dim
constexpr int T = 64;
constexpr int O = 64;
constexpr int P = T * O;            // 4096 pairs per batch
constexpr int OUT_D = 2 * D + E;    // 1664 floats per output row
constexpr int D4 = D / 4;           // 192 float4
constexpr int E4 = E / 4;           // 32 float4
constexpr int OUT_D4 = OUT_D / 4;   // 416 float4
constexpr int NBINS = 14;

// bucket = (# bins <= width) - 1; bins[0]=0 and width>=0,
// so bucket = sum_{i=1..13} (width >= bins[i]).
__constant__ int c_bins[NBINS] = {0, 1, 2, 3, 4, 5, 7, 8, 15, 16, 31, 32, 63, 64};

__device__ __forceinline__ int bucketize(int w) {
    int bucket = 0;
#pragma unroll
    for (int i = 1; i < NBINS; ++i)
        bucket += (w >= c_bins[i]) ? 1 : 0;
    return bucket;
}

// Champion R4 structure (2 rows/block: same target, adjacent opinions;
// 32768 blocks x 192 threads; __stcs streaming stores) with one refinement:
// stores are issued as soon as their producing load lands (vt stores overlap
// the in-flight voA/voB loads) instead of joining on all loads first. This
// de-bursts the store stream feeding the DRAM write path, which is the
// measured bottleneck (~7.05 TB/s effective writes = ~99% of achievable).
__global__ __launch_bounds__(192, 10)
void pair_rep_kernel(const float4* __restrict__ spans,      // [B,S,D/4]
                     const float4* __restrict__ dist_emb,   // [14,E/4]
                     const int2*   __restrict__ span_idx,   // [S]
                     const int*    __restrict__ tgt,        // [B,T]
                     const int*    __restrict__ opi,        // [B,O]
                     float4*       __restrict__ out)        // [B*P, OUT_D/4]
{
    const int blk = blockIdx.x;            // 0 .. B*T*(O/2)-1
    const int b   = blk >> 11;             // / 2048
    const int r   = blk & 2047;
    const int t   = r >> 5;                // / 32
    const int g   = r & 31;                // opinion pair group
    const int o0  = 2 * g;

    const int ti  = __ldg(&tgt[b * T + t]);
    const int oiA = __ldg(&opi[b * O + o0]);
    const int oiB = __ldg(&opi[b * O + o0 + 1]);

    const int tid = threadIdx.x;           // 0..191 == D4
    const float4* spb = spans + (size_t)b * S * D4;

    // Issue all span loads back-to-back (3 independent loads in flight)
    const float4 vt  = __ldg(&spb[(size_t)ti  * D4 + tid]);
    const float4 voA = __ldg(&spb[(size_t)oiA * D4 + tid]);
    const float4 voB = __ldg(&spb[(size_t)oiB * D4 + tid]);

    // Dist lanes: start their (L1/L2-hot) loads too, before any store joins
    float4 vdA, vdB;
    if (tid < E4) {
        const int2 ab  = __ldg(&span_idx[ti]);
        const int2 cdA = __ldg(&span_idx[oiA]);
        const int2 cdB = __ldg(&span_idx[oiB]);
        const int bkA = bucketize(min(abs(ab.y - cdA.x), abs(ab.x - cdA.y)));
        const int bkB = bucketize(min(abs(ab.y - cdB.x), abs(ab.x - cdB.y)));
        vdA = __ldg(&dist_emb[(size_t)bkA * E4 + tid]);
        vdB = __ldg(&dist_emb[(size_t)bkB * E4 + tid]);
    }

    float4* dst = out + ((size_t)b * P + (size_t)t * O + o0) * OUT_D4;

    // Store as soon as each producer lands: vt stores only wait on the vt
    // load (voA/voB still in flight), then voA, then voB, then dist.
    __stcs(&dst[tid], vt);                       // row A span_t
    __stcs(&dst[OUT_D4 + tid], vt);              // row B span_t
    __stcs(&dst[D4 + tid], voA);                 // row A span_o
    __stcs(&dst[OUT_D4 + D4 + tid], voB);        // row B span_o
    if (tid < E4) {
        __stcs(&dst[2 * D4 + tid], vdA);         // row A dist
        __stcs(&dst[OUT_D4 + 2 * D4 + tid], vdB);// row B dist
    }
}

extern "C" void kernel_launch(void* const* d_in, const int* in_sizes, int n_in,
                              void* d_out, int out_size)
{
    // metadata order: spans, dist_emb, span_indices, target_indices, opinion_indices
    const float4* spans    = (const float4*)d_in[0];
    const float4* dist_emb = (const float4*)d_in[1];
    const int2*   span_idx = (const int2*)  d_in[2];
    const int*    tgt      = (const int*)   d_in[3];
    const int*    opi      = (const int*)   d_in[4];
    float4*       out      = (float4*)d_out;

    dim3 grid(B * T * (O / 2));   // 32768 blocks, two rows each
    dim3 block(192);
    pair_rep_kernel<<<grid, block>>>(spans, dist_emb, span_idx, tgt, opi, out);
}